// round 2
// baseline (speedup 1.0000x reference)
#include <cuda_runtime.h>
#include <cstdint>

#define BT   16      // batch rows per block
#define NTH  256     // threads per block
#define HPAD 132     // row stride for h/c/x buffers (floats)
#define GPAD 17      // row stride for gate/pre buffers (floats)

// smem layout (floats)
#define OFF_X    0
#define OFF_H1   (OFF_X  + BT*HPAD)
#define OFF_C1   (OFF_H1 + BT*HPAD)
#define OFF_H2   (OFF_C1 + BT*HPAD)
#define OFF_C2   (OFF_H2 + BT*HPAD)
#define OFF_G    (OFF_C2 + BT*HPAD)           // [512][GPAD]
#define OFF_PRE  (OFF_G  + 512*GPAD)          // [512][GPAD]
#define SMEM_FLOATS (OFF_PRE + 512*GPAD)
#define SMEM_BYTES  (SMEM_FLOATS * 4)

__device__ __forceinline__ float tanha(float x) {
    float y;
    asm("tanh.approx.f32 %0, %1;" : "=f"(y) : "f"(x));
    return y;
}
__device__ __forceinline__ float sigm(float x) {
    return 0.5f * tanha(0.5f * x) + 0.5f;
}

// acc{0,1}[r] += sum_h hbuf[r][h] * W[j{0,1}][h], W row-major [512][128]
__device__ __forceinline__ void mm_acc(float* acc0, float* acc1,
                                       const float* __restrict__ W,
                                       int j0, int j1,
                                       const float* hbuf)
{
    const float4* w0p = reinterpret_cast<const float4*>(W + (size_t)j0 * 128);
    const float4* w1p = reinterpret_cast<const float4*>(W + (size_t)j1 * 128);
#pragma unroll 2
    for (int k = 0; k < 32; k++) {
        float4 w0 = w0p[k];
        float4 w1 = w1p[k];
#pragma unroll
        for (int r = 0; r < BT; r++) {
            float4 hv = *reinterpret_cast<const float4*>(hbuf + r * HPAD + 4 * k);
            acc0[r] = fmaf(hv.x, w0.x, acc0[r]);
            acc0[r] = fmaf(hv.y, w0.y, acc0[r]);
            acc0[r] = fmaf(hv.z, w0.z, acc0[r]);
            acc0[r] = fmaf(hv.w, w0.w, acc0[r]);
            acc1[r] = fmaf(hv.x, w1.x, acc1[r]);
            acc1[r] = fmaf(hv.y, w1.y, acc1[r]);
            acc1[r] = fmaf(hv.z, w1.z, acc1[r]);
            acc1[r] = fmaf(hv.w, w1.w, acc1[r]);
        }
    }
}

__global__ void __launch_bounds__(NTH, 2)
traj_decoder_kernel(const float* __restrict__ fused,
                    const float* __restrict__ intent,
                    const float* __restrict__ W_init, const float* __restrict__ b_init,
                    const float* __restrict__ W_ih0,  const float* __restrict__ W_hh0,
                    const float* __restrict__ b_ih0,  const float* __restrict__ b_hh0,
                    const float* __restrict__ W_ih1,  const float* __restrict__ W_hh1,
                    const float* __restrict__ b_ih1,  const float* __restrict__ b_hh1,
                    const float* __restrict__ W_o,    const float* __restrict__ b_o,
                    float* __restrict__ out, int Bn)
{
    extern __shared__ float sm[];
    float* x_s   = sm + OFF_X;
    float* h1_s  = sm + OFF_H1;
    float* c1_s  = sm + OFF_C1;
    float* h2_s  = sm + OFF_H2;
    float* c2_s  = sm + OFF_C2;
    float* g_s   = sm + OFF_G;
    float* pre_s = sm + OFF_PRE;

    const int t     = threadIdx.x;
    const int b0    = blockIdx.x * BT;
    const int hh    = t & 127;
    const int rbase = (t >> 7) * 8;
    const int j0 = t, j1 = t + 256;

    // ---------------- prologue: init GEMM (the torch-reshape quirk) ----------------
    // batch b uses init rows b/2 (layer0) and Bn/2 + b/2 (layer1);
    // this block needs init rows [b0/2, b0/2+8) and [Bn/2+b0/2, Bn/2+b0/2+8)
    for (int idx = t; idx < BT * 129; idx += NTH) {
        int ri = idx / 129, d = idx - ri * 129;
        int gr = (ri < 8) ? (b0 / 2 + ri) : (Bn / 2 + b0 / 2 + (ri - 8));
        float v = (d < 128) ? fused[(size_t)gr * 128 + d] : intent[gr];
        x_s[ri * HPAD + d] = v;
    }
    __syncthreads();

    {   // init matmul -> g_s  (W_init is [512][129], scalar loads: stride 129 breaks float4)
        float acc0[BT], acc1[BT];
        float bi0 = b_init[j0], bi1 = b_init[j1];
#pragma unroll
        for (int r = 0; r < BT; r++) { acc0[r] = bi0; acc1[r] = bi1; }
        const float* w0p = W_init + (size_t)j0 * 129;
        const float* w1p = W_init + (size_t)j1 * 129;
        for (int d = 0; d < 129; d++) {
            float w0 = w0p[d], w1 = w1p[d];
#pragma unroll
            for (int r = 0; r < BT; r++) {
                float xv = x_s[r * HPAD + d];
                acc0[r] = fmaf(xv, w0, acc0[r]);
                acc1[r] = fmaf(xv, w1, acc1[r]);
            }
        }
#pragma unroll
        for (int r = 0; r < BT; r++) {
            g_s[j0 * GPAD + r] = acc0[r];
            g_s[j1 * GPAD + r] = acc1[r];
        }
    }
    __syncthreads();

    // scatter init -> h/c states
#pragma unroll
    for (int k = 0; k < 8; k++) {
        int rl = rbase + k;
        int ri = rl >> 1;
        int jb = (rl & 1) * 128 + hh;
        h1_s[rl * HPAD + hh] = g_s[jb * GPAD + ri];
        c1_s[rl * HPAD + hh] = g_s[(jb + 256) * GPAD + ri];
        h2_s[rl * HPAD + hh] = g_s[jb * GPAD + (ri + 8)];
        c2_s[rl * HPAD + hh] = g_s[(jb + 256) * GPAD + (ri + 8)];
    }
    __syncthreads();

    // ---------------- prologue: pre0 = x @ W_ih0^T + b_ih0 + b_hh0 ----------------
    for (int idx = t; idx < BT * 129; idx += NTH) {
        int ri = idx / 129, d = idx - ri * 129;
        int gr = b0 + ri;
        float v = (d < 128) ? fused[(size_t)gr * 128 + d] : intent[gr];
        x_s[ri * HPAD + d] = v;
    }
    __syncthreads();

    {
        float acc0[BT], acc1[BT];
        float bi0 = b_ih0[j0] + b_hh0[j0];
        float bi1 = b_ih0[j1] + b_hh0[j1];
#pragma unroll
        for (int r = 0; r < BT; r++) { acc0[r] = bi0; acc1[r] = bi1; }
        const float* w0p = W_ih0 + (size_t)j0 * 129;
        const float* w1p = W_ih0 + (size_t)j1 * 129;
        for (int d = 0; d < 129; d++) {
            float w0 = w0p[d], w1 = w1p[d];
#pragma unroll
            for (int r = 0; r < BT; r++) {
                float xv = x_s[r * HPAD + d];
                acc0[r] = fmaf(xv, w0, acc0[r]);
                acc1[r] = fmaf(xv, w1, acc1[r]);
            }
        }
#pragma unroll
        for (int r = 0; r < BT; r++) {
            pre_s[j0 * GPAD + r] = acc0[r];
            pre_s[j1 * GPAD + r] = acc1[r];
        }
    }

    const float bias1a = b_ih1[j0] + b_hh1[j0];
    const float bias1b = b_ih1[j1] + b_hh1[j1];
    __syncthreads();

    // ---------------- 12 decode steps ----------------
    for (int s = 0; s < 12; s++) {
        // ---- layer 0: g = pre0 + h1 @ W_hh0^T ----
        {
            float acc0[BT], acc1[BT];
#pragma unroll
            for (int r = 0; r < BT; r++) {
                acc0[r] = pre_s[j0 * GPAD + r];
                acc1[r] = pre_s[j1 * GPAD + r];
            }
            mm_acc(acc0, acc1, W_hh0, j0, j1, h1_s);
#pragma unroll
            for (int r = 0; r < BT; r++) {
                g_s[j0 * GPAD + r] = acc0[r];
                g_s[j1 * GPAD + r] = acc1[r];
            }
        }
        __syncthreads();
        // gates layer 0
#pragma unroll
        for (int k = 0; k < 8; k++) {
            int rl = rbase + k;
            float iv = g_s[hh * GPAD + rl];
            float fv = g_s[(hh + 128) * GPAD + rl];
            float gv = g_s[(hh + 256) * GPAD + rl];
            float ov = g_s[(hh + 384) * GPAD + rl];
            float c  = sigm(fv) * c1_s[rl * HPAD + hh] + sigm(iv) * tanha(gv);
            float h  = sigm(ov) * tanha(c);
            c1_s[rl * HPAD + hh] = c;
            h1_s[rl * HPAD + hh] = h;
        }
        __syncthreads();

        // ---- layer 1: g = (b_ih1+b_hh1) + h1 @ W_ih1^T + h2 @ W_hh1^T ----
        {
            float acc0[BT], acc1[BT];
#pragma unroll
            for (int r = 0; r < BT; r++) { acc0[r] = bias1a; acc1[r] = bias1b; }
            mm_acc(acc0, acc1, W_ih1, j0, j1, h1_s);
            mm_acc(acc0, acc1, W_hh1, j0, j1, h2_s);
#pragma unroll
            for (int r = 0; r < BT; r++) {
                g_s[j0 * GPAD + r] = acc0[r];
                g_s[j1 * GPAD + r] = acc1[r];
            }
        }
        __syncthreads();
        // gates layer 1
#pragma unroll
        for (int k = 0; k < 8; k++) {
            int rl = rbase + k;
            float iv = g_s[hh * GPAD + rl];
            float fv = g_s[(hh + 128) * GPAD + rl];
            float gv = g_s[(hh + 256) * GPAD + rl];
            float ov = g_s[(hh + 384) * GPAD + rl];
            float c  = sigm(fv) * c2_s[rl * HPAD + hh] + sigm(iv) * tanha(gv);
            float h  = sigm(ov) * tanha(c);
            c2_s[rl * HPAD + hh] = c;
            h2_s[rl * HPAD + hh] = h;
        }
        __syncthreads();

        // ---- output head: out[b][s][k] = h2 . W_o[k] + b_o[k]  (warp 0 only) ----
        if (t < 32) {
            int r = t & 15, kk = t >> 4;
            float acc = b_o[kk];
            const float* wo = W_o + kk * 128;
            const float* hrow = h2_s + r * HPAD;
#pragma unroll 8
            for (int h = 0; h < 128; h++) acc = fmaf(hrow[h], wo[h], acc);
            out[((size_t)(b0 + r) * 12 + s) * 2 + kk] = acc;
        }
        // next-step L0 matmul only reads h1_s (stable) and rewrites g_s after all
        // threads passed the gate-1 sync, so no extra barrier is needed here.
    }
}

extern "C" void kernel_launch(void* const* d_in, const int* in_sizes, int n_in,
                              void* d_out, int out_size)
{
    const float* fused  = (const float*)d_in[0];
    const float* intent = (const float*)d_in[1];
    const float* W_init = (const float*)d_in[2];
    const float* b_init = (const float*)d_in[3];
    const float* W_ih0  = (const float*)d_in[4];
    const float* W_hh0  = (const float*)d_in[5];
    const float* b_ih0  = (const float*)d_in[6];
    const float* b_hh0  = (const float*)d_in[7];
    const float* W_ih1  = (const float*)d_in[8];
    const float* W_hh1  = (const float*)d_in[9];
    const float* b_ih1  = (const float*)d_in[10];
    const float* b_hh1  = (const float*)d_in[11];
    const float* W_o    = (const float*)d_in[12];
    const float* b_o    = (const float*)d_in[13];
    float* out = (float*)d_out;

    int Bn = in_sizes[0] / 128;

    cudaFuncSetAttribute(traj_decoder_kernel,
                         cudaFuncAttributeMaxDynamicSharedMemorySize, SMEM_BYTES);

    int grid = Bn / BT;
    traj_decoder_kernel<<<grid, NTH, SMEM_BYTES>>>(
        fused, intent, W_init, b_init,
        W_ih0, W_hh0, b_ih0, b_hh0,
        W_ih1, W_hh1, b_ih1, b_hh1,
        W_o, b_o, out, Bn);
}

// round 3
// speedup vs baseline: 1.4533x; 1.4533x over previous
#include <cuda_runtime.h>
#include <cstdint>

typedef unsigned long long ull;

#define NTH   512
#define BT    64          // batches per block
#define SEQ   12

// transposed-weight scratch layout (floats)
#define WT_L0    0                        // [128][512]  W_hh0^T
#define WT_L1    (WT_L0 + 128*512)        // [256][512]  [W_ih1 ; W_hh1]^T
#define WT_INIT  (WT_L1 + 256*512)        // [129][512]  W_init^T
#define WT_IH0   (WT_INIT + 129*512)      // [129][512]  W_ih0^T
#define WT_TOTAL (WT_IH0 + 129*512)

__device__ float g_Wt[WT_TOTAL];
// pre0 in accumulator layout: [blk][warp16][idx16][half2][lane32] as f32x2
__device__ ull   g_pre[(131072/BT) * 16 * 16 * 2 * 32];

// smem offsets (floats)
#define SM_H     0                        // hT1|hT2  [256][64]
#define SM_C1    (SM_H  + 256*64)         // [128][64]
#define SM_C2    (SM_C1 + 128*64)
#define SM_XT    (SM_C2 + 128*64)         // [129][64]
#define SM_B1D   (SM_XT + 129*64)         // 256 ull = 512 floats (8B aligned: offset even)
#define SM_WO    (SM_B1D + 512)           // [2][128]
#define SM_BO    (SM_WO + 256)            // [2]
#define SM_FLOATS (SM_BO + 2)
#define SMEM_BYTES (SM_FLOATS * 4)

__device__ __forceinline__ ull make2(float lo, float hi) {
    ull d; asm("mov.b64 %0, {%1, %2};" : "=l"(d) : "f"(lo), "f"(hi)); return d;
}
__device__ __forceinline__ void unpk(ull v, float& lo, float& hi) {
    asm("mov.b64 {%0, %1}, %2;" : "=f"(lo), "=f"(hi) : "l"(v));
}
__device__ __forceinline__ void fma2(ull& d, ull a, ull b) {
    asm("fma.rn.f32x2 %0, %1, %2, %0;" : "+l"(d) : "l"(a), "l"(b));
}
__device__ __forceinline__ void ldg128(const float* p, ull& a, ull& b) {
    asm("ld.global.nc.v2.u64 {%0, %1}, [%2];" : "=l"(a), "=l"(b) : "l"(p));
}
__device__ __forceinline__ float tanha(float x) {
    float y; asm("tanh.approx.f32 %0, %1;" : "=f"(y) : "f"(x)); return y;
}
__device__ __forceinline__ float sigm(float x) { return 0.5f * tanha(0.5f * x) + 0.5f; }

// ---------------- weight transpose prologue kernel ----------------
__global__ void transpose_weights(const float* __restrict__ W_init,
                                  const float* __restrict__ W_ih0,
                                  const float* __restrict__ W_hh0,
                                  const float* __restrict__ W_ih1,
                                  const float* __restrict__ W_hh1)
{
    int idx = blockIdx.x * blockDim.x + threadIdx.x;
    if (idx >= WT_TOTAL) return;
    float v;
    if (idx < WT_L1) {                       // W_hh0^T [128][512]
        int r = idx, k = r / 512, j = r % 512;
        v = W_hh0[j * 128 + k];
    } else if (idx < WT_INIT) {              // [W_ih1;W_hh1]^T [256][512]
        int r = idx - WT_L1, k = r / 512, j = r % 512;
        v = (k < 128) ? W_ih1[j * 128 + k] : W_hh1[j * 128 + (k - 128)];
    } else if (idx < WT_IH0) {               // W_init^T [129][512]
        int r = idx - WT_INIT, k = r / 512, j = r % 512;
        v = W_init[j * 129 + k];
    } else {                                 // W_ih0^T [129][512]
        int r = idx - WT_IH0, k = r / 512, j = r % 512;
        v = W_ih0[j * 129 + k];
    }
    g_Wt[idx] = v;
}

// ---------------- main fused kernel ----------------
struct Acc { ull a[4][4][2]; };   // [gate][h-pair][batch-half]

// acc += hbuf[k][b] * Wt[k][j]  for this thread's 32 columns, 2 batches
__device__ __forceinline__ void mm(const float* __restrict__ Wt,
                                   const float* __restrict__ hbuf,
                                   int klen, int w8, int l, Acc& A)
{
    const float* wbase = Wt + w8;   // + g*128 per gate
#pragma unroll 2
    for (int k = 0; k < klen; k++) {
        float ha = hbuf[k * 64 + l];
        float hb = hbuf[k * 64 + l + 32];
        ull da = make2(ha, ha);
        ull db = make2(hb, hb);
        const float* wk = wbase + k * 512;
#pragma unroll
        for (int g = 0; g < 4; g++) {
            ull w0, w1, w2, w3;
            ldg128(wk + g * 128,     w0, w1);
            ldg128(wk + g * 128 + 4, w2, w3);
            fma2(A.a[g][0][0], w0, da); fma2(A.a[g][0][1], w0, db);
            fma2(A.a[g][1][0], w1, da); fma2(A.a[g][1][1], w1, db);
            fma2(A.a[g][2][0], w2, da); fma2(A.a[g][2][1], w2, db);
            fma2(A.a[g][3][0], w3, da); fma2(A.a[g][3][1], w3, db);
        }
    }
}

__global__ void __launch_bounds__(NTH, 1)
traj_decoder_kernel(const float* __restrict__ fused,
                    const float* __restrict__ intent,
                    const float* __restrict__ b_init,
                    const float* __restrict__ b_ih0, const float* __restrict__ b_hh0,
                    const float* __restrict__ b_ih1, const float* __restrict__ b_hh1,
                    const float* __restrict__ W_o,   const float* __restrict__ b_o,
                    float* __restrict__ out, int Bn)
{
    extern __shared__ float sm[];
    float* hT  = sm + SM_H;        // hT1 = hT, hT2 = hT + 8192
    float* cT1 = sm + SM_C1;
    float* cT2 = sm + SM_C2;
    float* xT  = sm + SM_XT;
    ull*   b1d = (ull*)(sm + SM_B1D);
    float* wo  = sm + SM_WO;
    float* bo  = sm + SM_BO;

    const int t  = threadIdx.x;
    const int w  = t >> 5;          // warp 0..15
    const int l  = t & 31;          // lane = batch half-index
    const int w8 = 8 * w;           // h-base of this warp
    const int b0 = blockIdx.x * BT;

    // ---- small constant staging ----
    if (t < 256) {
        wo[t] = W_o[t];
        float blo = b_ih1[2 * t]     + b_hh1[2 * t];
        float bhi = b_ih1[2 * t + 1] + b_hh1[2 * t + 1];
        b1d[t] = make2(blo, bhi);
        if (t < 2) bo[t] = b_o[t];
    }

    // ---- phase 1: init GEMM over the reshape-quirk rows ----
    // row rr<32 -> init row b0/2+rr (layer0); rr>=32 -> Bn/2+b0/2+(rr-32) (layer1)
    for (int idx = t; idx < 129 * 64; idx += NTH) {
        int k = idx >> 6, rr = idx & 63;
        int R = (rr < 32) ? (b0 / 2 + rr) : (Bn / 2 + b0 / 2 + (rr - 32));
        xT[k * 64 + rr] = (k < 128) ? fused[(size_t)R * 128 + k] : intent[R];
    }
    __syncthreads();

    {
        Acc A;
#pragma unroll
        for (int g = 0; g < 4; g++)
#pragma unroll
            for (int p = 0; p < 4; p++) {
                ull bi = make2(b_init[g * 128 + w8 + 2 * p],
                               b_init[g * 128 + w8 + 2 * p + 1]);
                A.a[g][p][0] = bi; A.a[g][p][1] = bi;
            }
        mm(g_Wt + WT_INIT, xT, 129, w8, l, A);
        __syncthreads();   // all reads of xT done before refill below

        // scatter: g<2 -> h-state, g>=2 -> c-state; odd g -> odd local batch
#pragma unroll
        for (int g = 0; g < 4; g++)
#pragma unroll
            for (int p = 0; p < 4; p++) {
                float v0l, v0h, v1l, v1h;
                unpk(A.a[g][p][0], v0l, v0h);   // row l     -> layer 0
                unpk(A.a[g][p][1], v1l, v1h);   // row l+32  -> layer 1
                int lb = 2 * l + (g & 1);
                int h0 = w8 + 2 * p, h1 = h0 + 1;
                if (g < 2) {
                    hT[h0 * 64 + lb] = v0l;  hT[h1 * 64 + lb] = v0h;
                    hT[8192 + h0 * 64 + lb] = v1l;  hT[8192 + h1 * 64 + lb] = v1h;
                } else {
                    cT1[h0 * 64 + lb] = v0l; cT1[h1 * 64 + lb] = v0h;
                    cT2[h0 * 64 + lb] = v1l; cT2[h1 * 64 + lb] = v1h;
                }
            }
    }

    // ---- phase 2: pre0 GEMM over the actual batch rows -> g_pre ----
    for (int idx = t; idx < 129 * 64; idx += NTH) {
        int k = idx >> 6, rr = idx & 63;
        int R = b0 + rr;
        xT[k * 64 + rr] = (k < 128) ? fused[(size_t)R * 128 + k] : intent[R];
    }
    __syncthreads();

    ull* preblk = g_pre + ((size_t)blockIdx.x * 16 + w) * 16 * 64;
    {
        Acc A;
#pragma unroll
        for (int g = 0; g < 4; g++)
#pragma unroll
            for (int p = 0; p < 4; p++) {
                int j = g * 128 + w8 + 2 * p;
                ull bi = make2(b_ih0[j] + b_hh0[j], b_ih0[j + 1] + b_hh0[j + 1]);
                A.a[g][p][0] = bi; A.a[g][p][1] = bi;
            }
        mm(g_Wt + WT_IH0, xT, 129, w8, l, A);
#pragma unroll
        for (int g = 0; g < 4; g++)
#pragma unroll
            for (int p = 0; p < 4; p++) {
                int i16 = g * 4 + p;
                preblk[(i16 * 2 + 0) * 32 + l] = A.a[g][p][0];
                preblk[(i16 * 2 + 1) * 32 + l] = A.a[g][p][1];
            }
    }
    __syncthreads();

    // ---- 12 decode steps ----
    for (int s = 0; s < SEQ; s++) {
        // L0: acc = pre0 + h1 @ W_hh0^T
        Acc A;
#pragma unroll
        for (int g = 0; g < 4; g++)
#pragma unroll
            for (int p = 0; p < 4; p++) {
                int i16 = g * 4 + p;
                A.a[g][p][0] = preblk[(i16 * 2 + 0) * 32 + l];
                A.a[g][p][1] = preblk[(i16 * 2 + 1) * 32 + l];
            }
        mm(g_Wt + WT_L0, hT, 128, w8, l, A);
        __syncthreads();   // everyone done reading old h1

        // gates layer 0 (in-warp, own h rows & own batches)
#pragma unroll
        for (int p = 0; p < 4; p++)
#pragma unroll
            for (int bb = 0; bb < 2; bb++) {
                float i0, i1, f0, f1, g0, g1, o0, o1;
                unpk(A.a[0][p][bb], i0, i1);
                unpk(A.a[1][p][bb], f0, f1);
                unpk(A.a[2][p][bb], g0, g1);
                unpk(A.a[3][p][bb], o0, o1);
                int b = l + 32 * bb;
                int h0 = w8 + 2 * p, h1 = h0 + 1;
                float c0 = sigm(f0) * cT1[h0 * 64 + b] + sigm(i0) * tanha(g0);
                float c1 = sigm(f1) * cT1[h1 * 64 + b] + sigm(i1) * tanha(g1);
                cT1[h0 * 64 + b] = c0;  cT1[h1 * 64 + b] = c1;
                hT[h0 * 64 + b] = sigm(o0) * tanha(c0);
                hT[h1 * 64 + b] = sigm(o1) * tanha(c1);
            }
        __syncthreads();   // new h1 visible

        // L1: acc = bias1 + h1 @ W_ih1^T + h2 @ W_hh1^T   (hT is [h1|h2], klen 256)
#pragma unroll
        for (int g = 0; g < 4; g++)
#pragma unroll
            for (int p = 0; p < 4; p++) {
                ull bi = b1d[g * 64 + (w8 >> 1) + p];
                A.a[g][p][0] = bi; A.a[g][p][1] = bi;
            }
        mm(g_Wt + WT_L1, hT, 256, w8, l, A);
        __syncthreads();   // everyone done reading old h2

        // gates layer 1
#pragma unroll
        for (int p = 0; p < 4; p++)
#pragma unroll
            for (int bb = 0; bb < 2; bb++) {
                float i0, i1, f0, f1, g0, g1, o0, o1;
                unpk(A.a[0][p][bb], i0, i1);
                unpk(A.a[1][p][bb], f0, f1);
                unpk(A.a[2][p][bb], g0, g1);
                unpk(A.a[3][p][bb], o0, o1);
                int b = l + 32 * bb;
                int h0 = w8 + 2 * p, h1 = h0 + 1;
                float c0 = sigm(f0) * cT2[h0 * 64 + b] + sigm(i0) * tanha(g0);
                float c1 = sigm(f1) * cT2[h1 * 64 + b] + sigm(i1) * tanha(g1);
                cT2[h0 * 64 + b] = c0;  cT2[h1 * 64 + b] = c1;
                hT[8192 + h0 * 64 + b] = sigm(o0) * tanha(c0);
                hT[8192 + h1 * 64 + b] = sigm(o1) * tanha(c1);
            }
        __syncthreads();   // new h2 visible (for out head + next L1)

        // output head: warps 0-3
        if (t < 128) {
            int b = t & 63, xy = t >> 6;
            float acc = bo[xy];
            const float* woq = wo + xy * 128;
            const float* h2 = hT + 8192;
#pragma unroll 8
            for (int h = 0; h < 128; h++)
                acc = fmaf(h2[h * 64 + b], woq[h], acc);
            out[((size_t)(b0 + b) * SEQ + s) * 2 + xy] = acc;
        }
        // next L0 reads hT (h1, unchanged until after its own post-mm sync) — safe
    }
}

extern "C" void kernel_launch(void* const* d_in, const int* in_sizes, int n_in,
                              void* d_out, int out_size)
{
    const float* fused  = (const float*)d_in[0];
    const float* intent = (const float*)d_in[1];
    const float* W_init = (const float*)d_in[2];
    const float* b_init = (const float*)d_in[3];
    const float* W_ih0  = (const float*)d_in[4];
    const float* W_hh0  = (const float*)d_in[5];
    const float* b_ih0  = (const float*)d_in[6];
    const float* b_hh0  = (const float*)d_in[7];
    const float* W_ih1  = (const float*)d_in[8];
    const float* W_hh1  = (const float*)d_in[9];
    const float* b_ih1  = (const float*)d_in[10];
    const float* b_hh1  = (const float*)d_in[11];
    const float* W_o    = (const float*)d_in[12];
    const float* b_o    = (const float*)d_in[13];
    float* out = (float*)d_out;

    int Bn = in_sizes[0] / 128;

    transpose_weights<<<(WT_TOTAL + 511) / 512, 512>>>(W_init, W_ih0, W_hh0, W_ih1, W_hh1);

    cudaFuncSetAttribute(traj_decoder_kernel,
                         cudaFuncAttributeMaxDynamicSharedMemorySize, SMEM_BYTES);
    traj_decoder_kernel<<<Bn / BT, NTH, SMEM_BYTES>>>(
        fused, intent, b_init, b_ih0, b_hh0, b_ih1, b_hh1, W_o, b_o, out, Bn);
}

// round 4
// speedup vs baseline: 2.0830x; 1.4333x over previous
#include <cuda_runtime.h>
#include <cstdint>

typedef unsigned long long ull;

#define NTH   512
#define BT    64          // batches per block
#define SEQ   12
#define KT    16          // k-rows per staged tile (tile = KT*512 floats = 32KB)

// transposed-weight scratch layout (floats), each region contiguous [k][512]
#define WT_L0    0                        // [128][512]  W_hh0^T
#define WT_L1    (WT_L0 + 128*512)        // [256][512]  [W_ih1 ; W_hh1]^T
#define WT_INIT  (WT_L1 + 256*512)        // [129][512]  W_init^T
#define WT_IH0   (WT_INIT + 129*512)      // [129][512]  W_ih0^T
#define WT_TOTAL (WT_IH0 + 129*512)

__device__ float g_Wt[WT_TOTAL];
// pre0 in accumulator layout: [blk][warp16][idx16][half2][lane32] as f32x2
__device__ ull   g_pre[(131072/BT) * 16 * 16 * 2 * 32];

// smem offsets (floats)
#define SM_H     0                        // hT1|hT2  [256][64]
#define SM_C1    (SM_H  + 256*64)         // [128][64]
#define SM_C2    (SM_C1 + 128*64)
#define SM_WBUF  (SM_C2 + 128*64)         // 2 x KT*512 floats (double buffer, 64KB)
#define SM_XT    SM_WBUF                  // prologue-only overlay [129][64] (8256 <= 16384)
#define SM_B1D   (SM_WBUF + 2*KT*512)     // 256 ull = 512 floats
#define SM_WO    (SM_B1D + 512)           // [2][128]
#define SM_BO    (SM_WO + 256)
#define SM_FLOATS (SM_BO + 2)
#define SMEM_BYTES (SM_FLOATS * 4)

__device__ __forceinline__ ull make2(float lo, float hi) {
    ull d; asm("mov.b64 %0, {%1, %2};" : "=l"(d) : "f"(lo), "f"(hi)); return d;
}
__device__ __forceinline__ void unpk(ull v, float& lo, float& hi) {
    asm("mov.b64 {%0, %1}, %2;" : "=f"(lo), "=f"(hi) : "l"(v));
}
__device__ __forceinline__ void fma2(ull& d, ull a, ull b) {
    asm("fma.rn.f32x2 %0, %1, %2, %0;" : "+l"(d) : "l"(a), "l"(b));
}
__device__ __forceinline__ void ldg128(const float* p, ull& a, ull& b) {
    asm("ld.global.nc.v2.u64 {%0, %1}, [%2];" : "=l"(a), "=l"(b) : "l"(p));
}
__device__ __forceinline__ float tanha(float x) {
    float y; asm("tanh.approx.f32 %0, %1;" : "=f"(y) : "f"(x)); return y;
}
__device__ __forceinline__ float sigm(float x) { return 0.5f * tanha(0.5f * x) + 0.5f; }

__device__ __forceinline__ void cp16(uint32_t saddr, const float* gaddr) {
    asm volatile("cp.async.cg.shared.global [%0], [%1], 16;"
                 :: "r"(saddr), "l"(gaddr) : "memory");
}
__device__ __forceinline__ void cp_commit() {
    asm volatile("cp.async.commit_group;" ::: "memory");
}
__device__ __forceinline__ void cp_wait0() {
    asm volatile("cp.async.wait_group 0;" ::: "memory");
}

// ---------------- weight transpose prologue kernel ----------------
__global__ void transpose_weights(const float* __restrict__ W_init,
                                  const float* __restrict__ W_ih0,
                                  const float* __restrict__ W_hh0,
                                  const float* __restrict__ W_ih1,
                                  const float* __restrict__ W_hh1)
{
    int idx = blockIdx.x * blockDim.x + threadIdx.x;
    if (idx >= WT_TOTAL) return;
    float v;
    if (idx < WT_L1) {                       // W_hh0^T [128][512]
        int r = idx, k = r / 512, j = r % 512;
        v = W_hh0[j * 128 + k];
    } else if (idx < WT_INIT) {              // [W_ih1;W_hh1]^T [256][512]
        int r = idx - WT_L1, k = r / 512, j = r % 512;
        v = (k < 128) ? W_ih1[j * 128 + k] : W_hh1[j * 128 + (k - 128)];
    } else if (idx < WT_IH0) {               // W_init^T [129][512]
        int r = idx - WT_INIT, k = r / 512, j = r % 512;
        v = W_init[j * 129 + k];
    } else {                                 // W_ih0^T [129][512]
        int r = idx - WT_IH0, k = r / 512, j = r % 512;
        v = W_ih0[j * 129 + k];
    }
    g_Wt[idx] = v;
}

// ---------------- main fused kernel ----------------
struct Acc { ull a[4][4][2]; };   // [gate][h-pair][batch-half]

// direct-LDG matvec accumulate (prologue only): acc += hbuf[k][b]*Wt[k][j]
__device__ __forceinline__ void mm_direct(const float* __restrict__ Wt,
                                          const float* __restrict__ hbuf,
                                          int klen, int w8, int l, Acc& A)
{
    const float* wbase = Wt + w8;
#pragma unroll 2
    for (int k = 0; k < klen; k++) {
        float ha = hbuf[k * 64 + l];
        float hb = hbuf[k * 64 + l + 32];
        ull da = make2(ha, ha);
        ull db = make2(hb, hb);
        const float* wk = wbase + k * 512;
#pragma unroll
        for (int g = 0; g < 4; g++) {
            ull w0, w1, w2, w3;
            ldg128(wk + g * 128,     w0, w1);
            ldg128(wk + g * 128 + 4, w2, w3);
            fma2(A.a[g][0][0], w0, da); fma2(A.a[g][0][1], w0, db);
            fma2(A.a[g][1][0], w1, da); fma2(A.a[g][1][1], w1, db);
            fma2(A.a[g][2][0], w2, da); fma2(A.a[g][2][1], w2, db);
            fma2(A.a[g][3][0], w3, da); fma2(A.a[g][3][1], w3, db);
        }
    }
}

// copy one KT*512-float contiguous tile global->smem; each thread 4x16B
__device__ __forceinline__ void cp_tile(uint32_t sbase, const float* __restrict__ g, int t)
{
#pragma unroll
    for (int i = 0; i < 4; i++) {
        int c = t + i * NTH;                  // chunk 0..2047
        cp16(sbase + (uint32_t)c * 16u, g + (size_t)c * 4);
    }
}

// staged matvec: weights streamed through smem double-buffer with cp.async
__device__ __forceinline__ void mm_staged(const float* __restrict__ Wg,   // contiguous [klen][512]
                                          const float* __restrict__ hbuf, // smem [klen][64]
                                          int ntiles,
                                          float* __restrict__ wbuf, uint32_t wbuf_s,
                                          int w8, int l, int t, Acc& A)
{
    cp_tile(wbuf_s, Wg, t);                   // tile 0 -> buf0
    cp_commit();
    for (int tt = 0; tt < ntiles; tt++) {
        cp_wait0();
        __syncthreads();                      // tile tt visible; buf[(tt+1)&1] free
        if (tt + 1 < ntiles) {
            cp_tile(wbuf_s + ((tt + 1) & 1) * (KT * 512 * 4),
                    Wg + (size_t)(tt + 1) * KT * 512, t);
            cp_commit();
        }
        const float* wb = wbuf + (tt & 1) * (KT * 512) + w8;
        const float* hb = hbuf + tt * KT * 64;
#pragma unroll 4
        for (int kk = 0; kk < KT; kk++) {
            float ha = hb[kk * 64 + l];
            float hv = hb[kk * 64 + l + 32];
            ull da = make2(ha, ha);
            ull db = make2(hv, hv);
            const float* wk = wb + kk * 512;
#pragma unroll
            for (int g = 0; g < 4; g++) {
                ulonglong2 u = *reinterpret_cast<const ulonglong2*>(wk + g * 128);
                ulonglong2 v = *reinterpret_cast<const ulonglong2*>(wk + g * 128 + 4);
                fma2(A.a[g][0][0], u.x, da); fma2(A.a[g][0][1], u.x, db);
                fma2(A.a[g][1][0], u.y, da); fma2(A.a[g][1][1], u.y, db);
                fma2(A.a[g][2][0], v.x, da); fma2(A.a[g][2][1], v.x, db);
                fma2(A.a[g][3][0], v.y, da); fma2(A.a[g][3][1], v.y, db);
            }
        }
    }
}

__global__ void __launch_bounds__(NTH, 1)
traj_decoder_kernel(const float* __restrict__ fused,
                    const float* __restrict__ intent,
                    const float* __restrict__ b_init,
                    const float* __restrict__ b_ih0, const float* __restrict__ b_hh0,
                    const float* __restrict__ b_ih1, const float* __restrict__ b_hh1,
                    const float* __restrict__ W_o,   const float* __restrict__ b_o,
                    float* __restrict__ out, int Bn)
{
    extern __shared__ float sm[];
    float* hT  = sm + SM_H;        // hT1 = hT, hT2 = hT + 8192
    float* cT1 = sm + SM_C1;
    float* cT2 = sm + SM_C2;
    float* wbf = sm + SM_WBUF;
    float* xT  = sm + SM_XT;       // overlays wbf during prologue
    ull*   b1d = (ull*)(sm + SM_B1D);
    float* wo  = sm + SM_WO;
    float* bo  = sm + SM_BO;

    const uint32_t wbf_s = (uint32_t)__cvta_generic_to_shared(wbf);

    const int t  = threadIdx.x;
    const int w  = t >> 5;
    const int l  = t & 31;
    const int w8 = 8 * w;
    const int b0 = blockIdx.x * BT;

    // ---- small constant staging ----
    if (t < 256) {
        wo[t] = W_o[t];
        float blo = b_ih1[2 * t]     + b_hh1[2 * t];
        float bhi = b_ih1[2 * t + 1] + b_hh1[2 * t + 1];
        b1d[t] = make2(blo, bhi);
        if (t < 2) bo[t] = b_o[t];
    }

    // ---- phase 1: init GEMM over the reshape-quirk rows ----
    for (int idx = t; idx < 129 * 64; idx += NTH) {
        int k = idx >> 6, rr = idx & 63;
        int R = (rr < 32) ? (b0 / 2 + rr) : (Bn / 2 + b0 / 2 + (rr - 32));
        xT[k * 64 + rr] = (k < 128) ? fused[(size_t)R * 128 + k] : intent[R];
    }
    __syncthreads();

    {
        Acc A;
#pragma unroll
        for (int g = 0; g < 4; g++)
#pragma unroll
            for (int p = 0; p < 4; p++) {
                ull bi = make2(b_init[g * 128 + w8 + 2 * p],
                               b_init[g * 128 + w8 + 2 * p + 1]);
                A.a[g][p][0] = bi; A.a[g][p][1] = bi;
            }
        mm_direct(g_Wt + WT_INIT, xT, 129, w8, l, A);
        __syncthreads();

#pragma unroll
        for (int g = 0; g < 4; g++)
#pragma unroll
            for (int p = 0; p < 4; p++) {
                float v0l, v0h, v1l, v1h;
                unpk(A.a[g][p][0], v0l, v0h);   // row l     -> layer 0
                unpk(A.a[g][p][1], v1l, v1h);   // row l+32  -> layer 1
                int lb = 2 * l + (g & 1);
                int h0 = w8 + 2 * p, h1 = h0 + 1;
                if (g < 2) {
                    hT[h0 * 64 + lb] = v0l;  hT[h1 * 64 + lb] = v0h;
                    hT[8192 + h0 * 64 + lb] = v1l;  hT[8192 + h1 * 64 + lb] = v1h;
                } else {
                    cT1[h0 * 64 + lb] = v0l; cT1[h1 * 64 + lb] = v0h;
                    cT2[h0 * 64 + lb] = v1l; cT2[h1 * 64 + lb] = v1h;
                }
            }
    }

    // ---- phase 2: pre0 GEMM over the actual batch rows -> g_pre ----
    for (int idx = t; idx < 129 * 64; idx += NTH) {
        int k = idx >> 6, rr = idx & 63;
        int R = b0 + rr;
        xT[k * 64 + rr] = (k < 128) ? fused[(size_t)R * 128 + k] : intent[R];
    }
    __syncthreads();

    ull* preblk = g_pre + ((size_t)blockIdx.x * 16 + w) * 16 * 64;
    {
        Acc A;
#pragma unroll
        for (int g = 0; g < 4; g++)
#pragma unroll
            for (int p = 0; p < 4; p++) {
                int j = g * 128 + w8 + 2 * p;
                ull bi = make2(b_ih0[j] + b_hh0[j], b_ih0[j + 1] + b_hh0[j + 1]);
                A.a[g][p][0] = bi; A.a[g][p][1] = bi;
            }
        mm_direct(g_Wt + WT_IH0, xT, 129, w8, l, A);
#pragma unroll
        for (int g = 0; g < 4; g++)
#pragma unroll
            for (int p = 0; p < 4; p++) {
                int i16 = g * 4 + p;
                preblk[(i16 * 2 + 0) * 32 + l] = A.a[g][p][0];
                preblk[(i16 * 2 + 1) * 32 + l] = A.a[g][p][1];
            }
    }
    __syncthreads();   // all pre0-mm xT reads done before wbuf staging clobbers it

    // ---- 12 decode steps ----
    for (int s = 0; s < SEQ; s++) {
        // L0: acc = pre0 + h1 @ W_hh0^T  (8 staged tiles)
        Acc A;
#pragma unroll
        for (int g = 0; g < 4; g++)
#pragma unroll
            for (int p = 0; p < 4; p++) {
                int i16 = g * 4 + p;
                A.a[g][p][0] = preblk[(i16 * 2 + 0) * 32 + l];
                A.a[g][p][1] = preblk[(i16 * 2 + 1) * 32 + l];
            }
        mm_staged(g_Wt + WT_L0, hT, 128 / KT, wbf, wbf_s, w8, l, t, A);
        __syncthreads();   // everyone done reading old h1

        // gates layer 0
#pragma unroll
        for (int p = 0; p < 4; p++)
#pragma unroll
            for (int bb = 0; bb < 2; bb++) {
                float i0, i1, f0, f1, g0, g1, o0, o1;
                unpk(A.a[0][p][bb], i0, i1);
                unpk(A.a[1][p][bb], f0, f1);
                unpk(A.a[2][p][bb], g0, g1);
                unpk(A.a[3][p][bb], o0, o1);
                int b = l + 32 * bb;
                int h0 = w8 + 2 * p, h1 = h0 + 1;
                float c0 = sigm(f0) * cT1[h0 * 64 + b] + sigm(i0) * tanha(g0);
                float c1 = sigm(f1) * cT1[h1 * 64 + b] + sigm(i1) * tanha(g1);
                cT1[h0 * 64 + b] = c0;  cT1[h1 * 64 + b] = c1;
                hT[h0 * 64 + b] = sigm(o0) * tanha(c0);
                hT[h1 * 64 + b] = sigm(o1) * tanha(c1);
            }
        __syncthreads();   // new h1 visible

        // L1: acc = bias1 + [h1|h2] @ [W_ih1;W_hh1]^T  (16 staged tiles)
#pragma unroll
        for (int g = 0; g < 4; g++)
#pragma unroll
            for (int p = 0; p < 4; p++) {
                ull bi = b1d[g * 64 + (w8 >> 1) + p];
                A.a[g][p][0] = bi; A.a[g][p][1] = bi;
            }
        mm_staged(g_Wt + WT_L1, hT, 256 / KT, wbf, wbf_s, w8, l, t, A);
        __syncthreads();   // everyone done reading old h2

        // gates layer 1
#pragma unroll
        for (int p = 0; p < 4; p++)
#pragma unroll
            for (int bb = 0; bb < 2; bb++) {
                float i0, i1, f0, f1, g0, g1, o0, o1;
                unpk(A.a[0][p][bb], i0, i1);
                unpk(A.a[1][p][bb], f0, f1);
                unpk(A.a[2][p][bb], g0, g1);
                unpk(A.a[3][p][bb], o0, o1);
                int b = l + 32 * bb;
                int h0 = w8 + 2 * p, h1 = h0 + 1;
                float c0 = sigm(f0) * cT2[h0 * 64 + b] + sigm(i0) * tanha(g0);
                float c1 = sigm(f1) * cT2[h1 * 64 + b] + sigm(i1) * tanha(g1);
                cT2[h0 * 64 + b] = c0;  cT2[h1 * 64 + b] = c1;
                hT[8192 + h0 * 64 + b] = sigm(o0) * tanha(c0);
                hT[8192 + h1 * 64 + b] = sigm(o1) * tanha(c1);
            }
        __syncthreads();   // new h2 visible (for out head + next L1)

        // output head: warps 0-3
        if (t < 128) {
            int b = t & 63, xy = t >> 6;
            float acc = bo[xy];
            const float* woq = wo + xy * 128;
            const float* h2 = hT + 8192;
#pragma unroll 8
            for (int h = 0; h < 128; h++)
                acc = fmaf(h2[h * 64 + b], woq[h], acc);
            out[((size_t)(b0 + b) * SEQ + s) * 2 + xy] = acc;
        }
    }
}

extern "C" void kernel_launch(void* const* d_in, const int* in_sizes, int n_in,
                              void* d_out, int out_size)
{
    const float* fused  = (const float*)d_in[0];
    const float* intent = (const float*)d_in[1];
    const float* W_init = (const float*)d_in[2];
    const float* b_init = (const float*)d_in[3];
    const float* W_ih0  = (const float*)d_in[4];
    const float* W_hh0  = (const float*)d_in[5];
    const float* b_ih0  = (const float*)d_in[6];
    const float* b_hh0  = (const float*)d_in[7];
    const float* W_ih1  = (const float*)d_in[8];
    const float* W_hh1  = (const float*)d_in[9];
    const float* b_ih1  = (const float*)d_in[10];
    const float* b_hh1  = (const float*)d_in[11];
    const float* W_o    = (const float*)d_in[12];
    const float* b_o    = (const float*)d_in[13];
    float* out = (float*)d_out;

    int Bn = in_sizes[0] / 128;

    transpose_weights<<<(WT_TOTAL + 511) / 512, 512>>>(W_init, W_ih0, W_hh0, W_ih1, W_hh1);

    cudaFuncSetAttribute(traj_decoder_kernel,
                         cudaFuncAttributeMaxDynamicSharedMemorySize, SMEM_BYTES);
    traj_decoder_kernel<<<Bn / BT, NTH, SMEM_BYTES>>>(
        fused, intent, b_init, b_ih0, b_hh0, b_ih1, b_hh1, W_o, b_o, out, Bn);
}